// round 5
// baseline (speedup 1.0000x reference)
#include <cuda_runtime.h>
#include <cstdint>

#define S_   64
#define W_   128
#define D_   256
#define HW_  256
#define G3W_ 768
#define HS_  512
#define G3S_ 1536
#define C_   13

// ---------------- scratch (device globals; no allocation allowed) ----------
__device__ float g_X [2097152];    // [w][s][d]           128*64*256
__device__ float g_GI[12582912];   // [d][w][s][768]      2*128*64*768
__device__ float g_H [4194304];    // [d][w][s][256]
__device__ float g_ssum[S_*HS_];         // [s][512]
__device__ float g_GIS[2*S_*G3S_];       // [d][s][1536]
__device__ float g_SE[S_*1024];          // [s][1024]
__device__ float g_US[S_*1024];          // [s][1024]

// ---------------- helpers --------------------------------------------------
__device__ __forceinline__ unsigned su32(const void* p) {
    return (unsigned)__cvta_generic_to_shared(p);
}
// fast inf-safe sigmoid: 1/(1+e^-x); MUFU.EX2 + MUFU.RCP, rel err ~1e-6
__device__ __forceinline__ float fsigm(float x) {
    return __frcp_rn(1.f + __expf(-x));
}
// fast inf-safe tanh via exp: tanh(|x|) = 1 - 2/(e^{2|x|}+1), restore sign
__device__ __forceinline__ float ftanh(float x) {
    float a = fabsf(x);
    float e = __expf(2.f * a);            // >= 1, may be +inf (safe)
    float t = 1.f - 2.f * __frcp_rn(e + 1.f);
    return copysignf(t, x);
}

// ---------------- 1. embedding gather --------------------------------------
__global__ void k_gather(const int* __restrict__ doc, const float* __restrict__ emb) {
    int q  = blockIdx.x * blockDim.x + threadIdx.x;   // over 524288 float4s
    int d4 = q & 63;
    int rs = q >> 6;            // = w*64 + s
    int s  = rs & 63, w = rs >> 6;
    int tok = doc[s * W_ + w];
    ((float4*)g_X)[q] = ((const float4*)emb)[(long)tok * 64 + d4];
}

// ---------------- 2a. fast 128x128x8 SGEMM: C = A @ B^T + bias -------------
__global__ __launch_bounds__(256, 2) void k_gemm128(
    const float* __restrict__ A, const float* __restrict__ B,
    const float* __restrict__ bias, float* __restrict__ C,
    int M, int N, int K,
    long sAz, long sBz, long sbz, long sCz)
{
    __shared__ float As[2][1056];   // [8][132] x 2
    __shared__ float Bs[2][1056];
    int t  = threadIdx.x;
    int z  = blockIdx.z;
    const float* Ab = A + z * sAz + (long)blockIdx.x * 128 * K;
    const float* Bb = B + z * sBz + (long)blockIdx.y * 128 * K;
    int r  = t >> 1;            // 0..127
    int kc = (t & 1) * 4;       // 0 or 4
    int tx = t & 15, ty = t >> 4;

    float4 av = *(const float4*)&Ab[(long)r * K + kc];
    float4 bv = *(const float4*)&Bb[(long)r * K + kc];
    As[0][(kc+0)*132+r] = av.x; As[0][(kc+1)*132+r] = av.y;
    As[0][(kc+2)*132+r] = av.z; As[0][(kc+3)*132+r] = av.w;
    Bs[0][(kc+0)*132+r] = bv.x; Bs[0][(kc+1)*132+r] = bv.y;
    Bs[0][(kc+2)*132+r] = bv.z; Bs[0][(kc+3)*132+r] = bv.w;
    __syncthreads();

    float acc[8][8] = {};
    int nb = K >> 3;
    for (int kb = 0; kb < nb; kb++) {
        if (kb + 1 < nb) {
            av = *(const float4*)&Ab[(long)r * K + (kb + 1) * 8 + kc];
            bv = *(const float4*)&Bb[(long)r * K + (kb + 1) * 8 + kc];
        }
        const float* Ac = As[kb & 1];
        const float* Bc = Bs[kb & 1];
#pragma unroll
        for (int k = 0; k < 8; k++) {
            float4 a0 = *(const float4*)&Ac[k*132 + ty*4];
            float4 a1 = *(const float4*)&Ac[k*132 + 64 + ty*4];
            float4 b0 = *(const float4*)&Bc[k*132 + tx*4];
            float4 b1 = *(const float4*)&Bc[k*132 + 64 + tx*4];
            float a[8] = {a0.x,a0.y,a0.z,a0.w,a1.x,a1.y,a1.z,a1.w};
            float b[8] = {b0.x,b0.y,b0.z,b0.w,b1.x,b1.y,b1.z,b1.w};
#pragma unroll
            for (int i = 0; i < 8; i++)
#pragma unroll
                for (int j = 0; j < 8; j++)
                    acc[i][j] = fmaf(a[i], b[j], acc[i][j]);
        }
        if (kb + 1 < nb) {
            int nx = (kb + 1) & 1;
            As[nx][(kc+0)*132+r] = av.x; As[nx][(kc+1)*132+r] = av.y;
            As[nx][(kc+2)*132+r] = av.z; As[nx][(kc+3)*132+r] = av.w;
            Bs[nx][(kc+0)*132+r] = bv.x; Bs[nx][(kc+1)*132+r] = bv.y;
            Bs[nx][(kc+2)*132+r] = bv.z; Bs[nx][(kc+3)*132+r] = bv.w;
        }
        __syncthreads();
    }

    const float* bp = bias + z * sbz + blockIdx.y * 128;
    float4 bq0 = *(const float4*)&bp[tx*4];
    float4 bq1 = *(const float4*)&bp[64 + tx*4];
#pragma unroll
    for (int i = 0; i < 8; i++) {
        int m = blockIdx.x * 128 + ((i < 4) ? ty*4 + i : 64 + ty*4 + (i-4));
        long base = z * sCz + (long)m * N + blockIdx.y * 128;
        float4 o0, o1;
        o0.x = acc[i][0]+bq0.x; o0.y = acc[i][1]+bq0.y;
        o0.z = acc[i][2]+bq0.z; o0.w = acc[i][3]+bq0.w;
        o1.x = acc[i][4]+bq1.x; o1.y = acc[i][5]+bq1.y;
        o1.z = acc[i][6]+bq1.z; o1.w = acc[i][7]+bq1.w;
        *(float4*)&C[base + tx*4]      = o0;
        *(float4*)&C[base + 64 + tx*4] = o1;
    }
}

// ---------------- 2b. fused word attention + sum over words ----------------
__global__ __launch_bounds__(256, 2) void k_uword(
    const float* __restrict__ waW, const float* __restrict__ wab)
{
    __shared__ float As[2][1056];
    __shared__ float Bs[2][1056];
    int t  = threadIdx.x;
    int s  = blockIdx.x;                 // sentence
    const float* Bb = waW + (long)blockIdx.y * 128 * HS_;
    int r  = t >> 1;                     // 0..127 (= word index for A)
    int kc = (t & 1) * 4;
    int tx = t & 15, ty = t >> 4;

    auto loadA = [&](int k0) -> float4 {
        int k   = k0 + kc;
        int dir = k >> 8;
        int hw  = k & 255;
        return *(const float4*)&g_H[((long)(dir * W_ + r) * S_ + s) * HW_ + hw];
    };

    float4 av = loadA(0);
    float4 bv = *(const float4*)&Bb[(long)r * HS_ + kc];
    As[0][(kc+0)*132+r] = av.x; As[0][(kc+1)*132+r] = av.y;
    As[0][(kc+2)*132+r] = av.z; As[0][(kc+3)*132+r] = av.w;
    Bs[0][(kc+0)*132+r] = bv.x; Bs[0][(kc+1)*132+r] = bv.y;
    Bs[0][(kc+2)*132+r] = bv.z; Bs[0][(kc+3)*132+r] = bv.w;
    __syncthreads();

    float acc[8][8] = {};
    const int nb = HS_ >> 3;   // 64
    for (int kb = 0; kb < nb; kb++) {
        if (kb + 1 < nb) {
            av = loadA((kb + 1) * 8);
            bv = *(const float4*)&Bb[(long)r * HS_ + (kb + 1) * 8 + kc];
        }
        const float* Ac = As[kb & 1];
        const float* Bc = Bs[kb & 1];
#pragma unroll
        for (int k = 0; k < 8; k++) {
            float4 a0 = *(const float4*)&Ac[k*132 + ty*4];
            float4 a1 = *(const float4*)&Ac[k*132 + 64 + ty*4];
            float4 b0 = *(const float4*)&Bc[k*132 + tx*4];
            float4 b1 = *(const float4*)&Bc[k*132 + 64 + tx*4];
            float a[8] = {a0.x,a0.y,a0.z,a0.w,a1.x,a1.y,a1.z,a1.w};
            float b[8] = {b0.x,b0.y,b0.z,b0.w,b1.x,b1.y,b1.z,b1.w};
#pragma unroll
            for (int i = 0; i < 8; i++)
#pragma unroll
                for (int j = 0; j < 8; j++)
                    acc[i][j] = fmaf(a[i], b[j], acc[i][j]);
        }
        if (kb + 1 < nb) {
            int nx = (kb + 1) & 1;
            As[nx][(kc+0)*132+r] = av.x; As[nx][(kc+1)*132+r] = av.y;
            As[nx][(kc+2)*132+r] = av.z; As[nx][(kc+3)*132+r] = av.w;
            Bs[nx][(kc+0)*132+r] = bv.x; Bs[nx][(kc+1)*132+r] = bv.y;
            Bs[nx][(kc+2)*132+r] = bv.z; Bs[nx][(kc+3)*132+r] = bv.w;
        }
        __syncthreads();
    }

    const float* bp = wab + blockIdx.y * 128;
    float rsum[8];
#pragma unroll
    for (int j = 0; j < 8; j++) {
        int col = (j < 4) ? tx*4 + j : 64 + tx*4 + (j-4);
        float bj = bp[col];
        float sum = 0.f;
#pragma unroll
        for (int i = 0; i < 8; i++) sum += ftanh(acc[i][j] + bj);
        rsum[j] = sum;
    }
    __syncthreads();
    float* red = &As[0][0];               // [16][132]
#pragma unroll
    for (int j = 0; j < 8; j++) {
        int col = (j < 4) ? tx*4 + j : 64 + tx*4 + (j-4);
        red[ty*132 + col] = rsum[j];
    }
    __syncthreads();
    if (t < 128) {
        float a = 0.f;
#pragma unroll
        for (int y = 0; y < 16; y++) a += red[y*132 + t];
        g_ssum[s * HS_ + blockIdx.y * 128 + t] = a;
    }
}

// ---------------- 2c. small generic GEMM (M=64 cases) ----------------------
#define BM 64
#define BN 64
#define BK 32
__global__ __launch_bounds__(256) void k_gemm(
    const float* __restrict__ A, const float* __restrict__ B,
    const float* __restrict__ bias, float* __restrict__ C,
    int M, int N, int K, int actTanh,
    long sAz, long sBz, long sbz, long sCz)
{
    __shared__ float As2[BK][BM + 1];
    __shared__ float Bs2[BK][BN + 1];
    int t  = threadIdx.x;
    int tx = t & 15, ty = t >> 4;
    int z  = blockIdx.z;
    const float* Ab = A + z * sAz + (long)blockIdx.x * BM * K;
    const float* Bb = B + z * sBz + (long)blockIdx.y * BN * K;
    float acc[4][4] = {};
    for (int k0 = 0; k0 < K; k0 += BK) {
#pragma unroll
        for (int j = 0; j < 8; j++) {
            int idx = j * 256 + t;
            int m = idx >> 5, k = idx & 31;
            As2[k][m] = Ab[(long)m * K + k0 + k];
            Bs2[k][m] = Bb[(long)m * K + k0 + k];
        }
        __syncthreads();
#pragma unroll 8
        for (int k = 0; k < BK; k++) {
            float a0 = As2[k][ty*4+0], a1 = As2[k][ty*4+1], a2 = As2[k][ty*4+2], a3 = As2[k][ty*4+3];
            float b0 = Bs2[k][tx*4+0], b1 = Bs2[k][tx*4+1], b2 = Bs2[k][tx*4+2], b3 = Bs2[k][tx*4+3];
            acc[0][0]=fmaf(a0,b0,acc[0][0]); acc[0][1]=fmaf(a0,b1,acc[0][1]);
            acc[0][2]=fmaf(a0,b2,acc[0][2]); acc[0][3]=fmaf(a0,b3,acc[0][3]);
            acc[1][0]=fmaf(a1,b0,acc[1][0]); acc[1][1]=fmaf(a1,b1,acc[1][1]);
            acc[1][2]=fmaf(a1,b2,acc[1][2]); acc[1][3]=fmaf(a1,b3,acc[1][3]);
            acc[2][0]=fmaf(a2,b0,acc[2][0]); acc[2][1]=fmaf(a2,b1,acc[2][1]);
            acc[2][2]=fmaf(a2,b2,acc[2][2]); acc[2][3]=fmaf(a2,b3,acc[2][3]);
            acc[3][0]=fmaf(a3,b0,acc[3][0]); acc[3][1]=fmaf(a3,b1,acc[3][1]);
            acc[3][2]=fmaf(a3,b2,acc[3][2]); acc[3][3]=fmaf(a3,b3,acc[3][3]);
        }
        __syncthreads();
    }
    const float* bp = bias + z * sbz;
#pragma unroll
    for (int i = 0; i < 4; i++) {
        int m = blockIdx.x * BM + ty * 4 + i;
#pragma unroll
        for (int j = 0; j < 4; j++) {
            int n = blockIdx.y * BN + tx * 4 + j;
            float v = acc[i][j] + bp[n];
            if (actTanh) v = ftanh(v);
            C[z * sCz + (long)m * N + n] = v;
        }
    }
}

// ---------------- 3. word GRU recurrence (cluster of 4) --------------------
#define PADK 260                                    // 260 % 32 == 4 -> conflict-free LDS.128
#define GRU_SMEM ((3*64*PADK + 2*4*256 + 192) * 4)  // 208640 B

extern __shared__ float smem_gru[];

__global__ void __cluster_dims__(4, 1, 1) __launch_bounds__(128, 1)
k_wordgru(const float* __restrict__ wWh, const float* __restrict__ wbh)
{
    float* Wsh  = smem_gru;                 // [3*64][PADK]
    float* hbuf = Wsh + 3 * 64 * PADK;      // [2][4][256]
    float* bhs  = hbuf + 2 * 4 * 256;       // [192]

    int rank = blockIdx.x & 3;
    int cid  = blockIdx.x >> 2;
    int d    = cid >> 4;
    int s0   = (cid & 15) * 4;
    int j0   = rank * 64;
    int tid  = threadIdx.x;

    const float4* w4g = (const float4*)wWh;
    for (int i = tid; i < 3 * 64 * 64; i += 128) {
        int g  = i >> 12;
        int r2 = i & 4095;
        int jj = r2 >> 6, k4 = r2 & 63;
        float4 v = w4g[((long)d * G3W_ + g * 256 + j0 + jj) * 64 + k4];
        *(float4*)&Wsh[(g * 64 + jj) * PADK + k4 * 4] = v;
    }
    for (int i = tid; i < 192; i += 128)
        bhs[i] = wbh[d * G3W_ + (i >> 6) * 256 + j0 + (i & 63)];
    for (int i = tid; i < 4 * 256; i += 128) hbuf[i] = 0.f;
    __syncthreads();
    asm volatile("barrier.cluster.arrive.aligned;" ::: "memory");
    asm volatile("barrier.cluster.wait.aligned;"   ::: "memory");

    int spair = tid >> 6;
    int jj    = tid & 63;
    int sA = spair * 2, sB = sA + 1;
    int dim = j0 + jj;
    float bhr = bhs[jj], bhz = bhs[64 + jj], bhn = bhs[128 + jj];
    const float4* wR = (const float4*)&Wsh[( 0 + jj) * PADK];
    const float4* wZ = (const float4*)&Wsh[( 64 + jj) * PADK];
    const float4* wN = (const float4*)&Wsh[(128 + jj) * PADK];

    // hoist DSMEM target addresses (constant per buffer parity)
    unsigned remA[2][4], remB[2][4];
#pragma unroll
    for (int b = 0; b < 2; b++) {
        unsigned laA = su32(&hbuf[(b * 4 + sA) * 256 + dim]);
        unsigned laB = su32(&hbuf[(b * 4 + sB) * 256 + dim]);
#pragma unroll
        for (int tcta = 0; tcta < 4; tcta++) {
            asm volatile("mapa.shared::cluster.u32 %0, %1, %2;"
                         : "=r"(remA[b][tcta]) : "r"(laA), "r"(tcta));
            asm volatile("mapa.shared::cluster.u32 %0, %1, %2;"
                         : "=r"(remB[b][tcta]) : "r"(laB), "r"(tcta));
        }
    }

    // GI base offsets for this thread's two sentences
    const long strideW = (long)S_ * G3W_;                     // per-word stride
    long gibA = ((long)(d * W_) * S_ + (s0 + sA)) * G3W_ + dim;
    long gibB = ((long)(d * W_) * S_ + (s0 + sB)) * G3W_ + dim;

    // prefetch step 0
    float pRA = g_GI[gibA], pZA = g_GI[gibA + 256], pNA = g_GI[gibA + 512];
    float pRB = g_GI[gibB], pZB = g_GI[gibB + 256], pNB = g_GI[gibB + 512];

    for (int w = 0; w < W_; w++) {
        int cur = w & 1, nxt = cur ^ 1;

        // consume prefetched GI, then immediately issue next step's loads
        float giRA = pRA, giZA = pZA, giNA = pNA;
        float giRB = pRB, giZB = pZB, giNB = pNB;
        {
            int wn = (w + 1 < W_) ? (w + 1) : w;       // clamp (harmless reload)
            long nA = gibA + (long)wn * strideW - (long)w * strideW + (long)w * 0; // keep simple below
            long a = gibA + strideW, b = gibB + strideW;
            if (w + 1 >= W_) { a = gibA; b = gibB; }
            pRA = __ldg(&g_GI[a]);       pZA = __ldg(&g_GI[a + 256]);
            pNA = __ldg(&g_GI[a + 512]);
            pRB = __ldg(&g_GI[b]);       pZB = __ldg(&g_GI[b + 256]);
            pNB = __ldg(&g_GI[b + 512]);
            (void)nA; (void)wn;
        }

        const float4* hA = (const float4*)&hbuf[(cur * 4 + sA) * 256];
        const float4* hB = (const float4*)&hbuf[(cur * 4 + sB) * 256];
        float aRA = 0, aZA = 0, aNA = 0, aRB = 0, aZB = 0, aNB = 0;
#pragma unroll 8
        for (int k4 = 0; k4 < 64; k4++) {
            float4 wr = wR[k4], wz = wZ[k4], wn = wN[k4];
            float4 ha = hA[k4], hb = hB[k4];
            aRA = fmaf(wr.x, ha.x, aRA); aRA = fmaf(wr.y, ha.y, aRA);
            aRA = fmaf(wr.z, ha.z, aRA); aRA = fmaf(wr.w, ha.w, aRA);
            aZA = fmaf(wz.x, ha.x, aZA); aZA = fmaf(wz.y, ha.y, aZA);
            aZA = fmaf(wz.z, ha.z, aZA); aZA = fmaf(wz.w, ha.w, aZA);
            aNA = fmaf(wn.x, ha.x, aNA); aNA = fmaf(wn.y, ha.y, aNA);
            aNA = fmaf(wn.z, ha.z, aNA); aNA = fmaf(wn.w, ha.w, aNA);
            aRB = fmaf(wr.x, hb.x, aRB); aRB = fmaf(wr.y, hb.y, aRB);
            aRB = fmaf(wr.z, hb.z, aRB); aRB = fmaf(wr.w, hb.w, aRB);
            aZB = fmaf(wz.x, hb.x, aZB); aZB = fmaf(wz.y, hb.y, aZB);
            aZB = fmaf(wz.z, hb.z, aZB); aZB = fmaf(wz.w, hb.w, aZB);
            aNB = fmaf(wn.x, hb.x, aNB); aNB = fmaf(wn.y, hb.y, aNB);
            aNB = fmaf(wn.z, hb.z, aNB); aNB = fmaf(wn.w, hb.w, aNB);
        }
        float holdA = hbuf[(cur * 4 + sA) * 256 + dim];
        float holdB = hbuf[(cur * 4 + sB) * 256 + dim];
        float rA = fsigm(giRA + aRA + bhr);
        float zA = fsigm(giZA + aZA + bhz);
        float nA = ftanh(giNA + rA * (aNA + bhn));
        float hpA = (1.f - zA) * nA + zA * holdA;
        float rB = fsigm(giRB + aRB + bhr);
        float zB = fsigm(giZB + aZB + bhz);
        float nB = ftanh(giNB + rB * (aNB + bhn));
        float hpB = (1.f - zB) * nB + zB * holdB;

        // DSMEM pushes first, then arrive (release), then overlap STG with barrier
#pragma unroll
        for (int tcta = 0; tcta < 4; tcta++) {
            asm volatile("st.shared::cluster.f32 [%0], %1;"
                         :: "r"(remA[nxt][tcta]), "f"(hpA) : "memory");
            asm volatile("st.shared::cluster.f32 [%0], %1;"
                         :: "r"(remB[nxt][tcta]), "f"(hpB) : "memory");
        }
        asm volatile("barrier.cluster.arrive.aligned;" ::: "memory");  // release

        g_H[((long)(d * W_ + w) * S_ + (s0 + sA)) * HW_ + dim] = hpA;
        g_H[((long)(d * W_ + w) * S_ + (s0 + sB)) * HW_ + dim] = hpB;

        gibA += strideW; gibB += strideW;

        asm volatile("barrier.cluster.wait.aligned;"   ::: "memory");  // acquire
    }
}

// ---------------- 6. sentence encoder pointwise (h0 = 0) -------------------
__global__ void k_sentenc(const float* __restrict__ sbh) {
    int idx = blockIdx.x * blockDim.x + threadIdx.x;  // 65536
    int d = idx >> 15;
    int s = (idx >> 9) & 63;
    int h = idx & 511;
    const float* gi = &g_GIS[(d * S_ + s) * G3S_];
    float r  = fsigm(gi[h]       + sbh[d * G3S_ + h]);
    float zz = fsigm(gi[512 + h] + sbh[d * G3S_ + 512 + h]);
    float n  = ftanh(gi[1024 + h] + r * sbh[d * G3S_ + 1024 + h]);
    g_SE[s * 1024 + d * 512 + h] = (1.f - zz) * n;
}

// ---------------- 7. outputs -----------------------------------------------
__global__ void k_ones(float* out, int n) {
    int i = blockIdx.x * 256 + threadIdx.x;
    if (i < n) out[i] = 1.0f;
}

__global__ void k_final(const float* __restrict__ doW, const float* __restrict__ dob,
                        float* __restrict__ out, int out_size) {
    __shared__ float doc[1024];
    __shared__ float red[256];
    __shared__ float logit[16];
    int t = threadIdx.x;
    for (int n = t; n < 1024; n += 256) {
        float a = 0.f;
        for (int s = 0; s < S_; s++) a += g_US[s * 1024 + n];
        doc[n] = a;
    }
    __syncthreads();
    for (int c = 0; c < C_; c++) {
        float p = 0.f;
        for (int n = t; n < 1024; n += 256) p = fmaf(doc[n], doW[c * 1024 + n], p);
        red[t] = p; __syncthreads();
        for (int st = 128; st > 0; st >>= 1) {
            if (t < st) red[t] += red[t + st];
            __syncthreads();
        }
        if (t == 0) logit[c] = red[0] + dob[c];
        __syncthreads();
    }
    if (t == 0) {
        float m = -1e30f;
        for (int c = 0; c < C_; c++) m = fmaxf(m, logit[c]);
        float se = 0.f;
        for (int c = 0; c < C_; c++) se += expf(logit[c] - m);   // keep accurate
        float lse = m + logf(se);
        for (int c = 0; c < C_; c++) out[out_size - C_ + c] = logit[c] - lse;
    }
}

// ---------------- launcher -------------------------------------------------
extern "C" void kernel_launch(void* const* d_in, const int* in_sizes, int n_in,
                              void* d_out, int out_size) {
    const int*   doc = (const int*)  d_in[0];
    const float* emb = (const float*)d_in[1];
    const float* wWi = (const float*)d_in[2];
    const float* wWh = (const float*)d_in[3];
    const float* wbi = (const float*)d_in[4];
    const float* wbh = (const float*)d_in[5];
    const float* sWi = (const float*)d_in[6];
    const float* sbi = (const float*)d_in[8];
    const float* sbh = (const float*)d_in[9];
    const float* waW = (const float*)d_in[10];
    const float* wab = (const float*)d_in[11];
    const float* saW = (const float*)d_in[13];
    const float* sab = (const float*)d_in[14];
    const float* doW = (const float*)d_in[16];
    const float* dob = (const float*)d_in[17];
    float* out = (float*)d_out;

    cudaFuncSetAttribute(k_wordgru, cudaFuncAttributeMaxDynamicSharedMemorySize, GRU_SMEM);

    float *pX, *pGI, *pS, *pGIS, *pSE, *pUS;
    cudaGetSymbolAddress((void**)&pX,  g_X);
    cudaGetSymbolAddress((void**)&pGI, g_GI);
    cudaGetSymbolAddress((void**)&pS,  g_ssum);
    cudaGetSymbolAddress((void**)&pGIS,g_GIS);
    cudaGetSymbolAddress((void**)&pSE, g_SE);
    cudaGetSymbolAddress((void**)&pUS, g_US);

    // 1. gather embeddings
    k_gather<<<2048, 256>>>(doc, emb);

    // 2. GI[d] = X @ wWi[d].T + wbi[d]   (M=8192, N=768, K=256)
    k_gemm128<<<dim3(64, 6, 2), 256>>>(pX, wWi, wbi, pGI, 8192, 768, 256,
                                       0, 768L * 256, 768, 8192L * 768);

    // 3. recurrence -> g_H
    k_wordgru<<<128, 128, GRU_SMEM>>>(wWh, wbh);

    // 4+5+6 fused: g_ssum[s] = sum_w tanh(wordenc[s,w] @ waW.T + wab)
    k_uword<<<dim3(64, 4), 256>>>(waW, wab);

    // 7. GIS[d] = sent_summ @ sWi[d].T + sbi[d]  (M=64, N=1536, K=512)
    k_gemm<<<dim3(1, 24, 2), 256>>>(pS, sWi, sbi, pGIS, 64, 1536, 512, 0,
                                    0, 1536L * 512, 1536, 64L * 1536);

    // 8. sentenc pointwise
    k_sentenc<<<256, 256>>>(sbh);

    // 9. u_sent = tanh(sentenc @ saW.T + sab)   (M=64, N=1024, K=1024)
    k_gemm<<<dim3(1, 16, 1), 256>>>(pSE, saW, sab, pUS, 64, 1024, 1024, 1, 0, 0, 0, 0);

    // 10. outputs
    int nOnes = out_size - C_;
    k_ones<<<(nOnes + 255) / 256, 256>>>(out, nOnes);
    k_final<<<1, 256>>>(doW, dob, out, out_size);
}